// round 13
// baseline (speedup 1.0000x reference)
#include <cuda_runtime.h>
#include <math.h>

#define Bn 16
#define Ln 4096
#define Cn 1024
#define Kn 16
#define NSPLIT 32
#define CHUNK 128
#define THREADS 256
#define TC 128
#define QSTRIDE 132
#define NEG_INF (__int_as_float(0xff800000))

typedef unsigned long long ull;

__device__ float g_acc[(size_t)Bn * NSPLIT * Kn * Cn];
__device__ float g_m[Bn * NSPLIT * Kn];
__device__ float g_d[Bn * NSPLIT * Kn];

__device__ __forceinline__ ull fma2(ull a, ull b, ull c) {
    ull d;
    asm("fma.rn.f32x2 %0, %1, %2, %3;" : "=l"(d) : "l"(a), "l"(b), "l"(c));
    return d;
}
__device__ __forceinline__ float2 unpack2(ull v) {
    float2 f;
    f.x = __uint_as_float((unsigned)(v & 0xffffffffULL));
    f.y = __uint_as_float((unsigned)(v >> 32));
    return f;
}
__device__ __forceinline__ ull pack2(float a, float b) {
    ull v;
    asm("mov.b64 %0, {%1, %2};" : "=l"(v) : "f"(a), "f"(b));
    return v;
}
__device__ __forceinline__ void cp_async16(unsigned int smem, const void* g) {
    asm volatile("cp.async.cg.shared.global [%0], [%1], 16;" :: "r"(smem), "l"(g));
}
__device__ __forceinline__ void cp_commit() {
    asm volatile("cp.async.commit_group;");
}
template <int N>
__device__ __forceinline__ void cp_wait() {
    asm volatile("cp.async.wait_group %0;" :: "n"(N) : "memory");
}

// SMEM offsets (total ~97KB -> 2 blocks/SM at 256 thr / 128 regs)
#define XS0   0                       // 64 l x 128 c fp32 = 32KB
#define XS1   32768
#define QS0   65536                   // 16 k x 132 floats = 8448B
#define QS1   73984
#define SSOFF 82432                   // scores [16 k][128 l] = 8KB
#define W2OFF 90624                   // weights [64 lp][16 k][2] floats = 8KB
#define MKOFF 98816                   // mask [128] int
#define SMEM_TOTAL 99328

extern "C" __global__ void __launch_bounds__(THREADS, 2)
pool_partial_kernel(const float* __restrict__ x,
                    const int* __restrict__ mask,
                    const float* __restrict__ q) {
    extern __shared__ char smem[];
    unsigned int smem_u32 = (unsigned int)__cvta_generic_to_shared(smem);
    float* s_s = (float*)(smem + SSOFF);
    int* mask_s = (int*)(smem + MKOFF);

    const int tid = threadIdx.x;
    const int w = tid >> 5;            // 8 warps
    const int lane = tid & 31;
    const int cg = lane & 7;
    const int kg = lane >> 3;
    const int b = blockIdx.x / NSPLIT;
    const int split = blockIdx.x % NSPLIT;
    const int l0 = split * CHUNK;
    const float* xbase = x + ((size_t)b * Ln + l0) * Cn;

    // ---- prefetch half-tile 0 (h=0, t=0): x rows 0-63, cols 0-127 + q tile 0 ----
    {
        unsigned int xd = smem_u32 + XS0;
#pragma unroll
        for (int r = 0; r < 8; ++r) {
            int id = tid + THREADS * r;          // 2048 float4
            int row = id >> 5, c4 = id & 31;
            cp_async16(xd + row * 512 + c4 * 16,
                       xbase + (size_t)row * Cn + c4 * 4);
        }
#pragma unroll
        for (int r = 0; r < 2; ++r) {
            int id = tid + THREADS * r;          // 512 float4
            int qrow = id >> 5, qc4 = id & 31;
            cp_async16(smem_u32 + QS0 + qrow * (QSTRIDE * 4) + qc4 * 16,
                       q + qrow * Cn + qc4 * 4);
        }
        cp_commit();
    }
    if (tid < CHUNK) mask_s[tid] = mask[b * Ln + l0 + tid];

    ull acc[8][4];
#pragma unroll
    for (int a = 0; a < 8; ++a)
#pragma unroll
        for (int i = 0; i < 4; ++i) acc[a][i] = 0ULL;

    // ------------- Phase A: 16 half-tiles (2 l-halves x 8 c-tiles) -------------
    for (int it = 0; it < 16; ++it) {
        const int h = it >> 3;
        if (it < 15) {
            const int itn = it + 1;
            const int hn = itn >> 3, tn = itn & 7;
            unsigned int xd = smem_u32 + ((itn & 1) ? XS1 : XS0);
#pragma unroll
            for (int r = 0; r < 8; ++r) {
                int id = tid + THREADS * r;
                int row = id >> 5, c4 = id & 31;
                cp_async16(xd + row * 512 + c4 * 16,
                           xbase + (size_t)(hn * 64 + row) * Cn + tn * TC + c4 * 4);
            }
#pragma unroll
            for (int r = 0; r < 2; ++r) {
                int id = tid + THREADS * r;
                int qrow = id >> 5, qc4 = id & 31;
                cp_async16(smem_u32 + ((itn & 1) ? QS1 : QS0) + qrow * (QSTRIDE * 4) + qc4 * 16,
                           q + qrow * Cn + tn * TC + qc4 * 4);
            }
            cp_commit();
            cp_wait<1>();
        } else {
            cp_wait<0>();
        }
        __syncthreads();

        const float* xs = (const float*)(smem + ((it & 1) ? XS1 : XS0));
        const float* qs = (const float*)(smem + ((it & 1) ? QS1 : QS0));

#pragma unroll
        for (int quad = 0; quad < 4; ++quad) {
            const int cof = cg * 4 + quad * 32;
            ulonglong2 qv[4];
#pragma unroll
            for (int i = 0; i < 4; ++i)
                qv[i] = *(const ulonglong2*)(qs + (kg * 4 + i) * QSTRIDE + cof);
#pragma unroll
            for (int j = 0; j < 8; ++j) {
                ulonglong2 xv = *(const ulonglong2*)(xs + (w * 8 + j) * TC + cof);
#pragma unroll
                for (int i = 0; i < 4; ++i) {
                    acc[j][i] = fma2(xv.x, qv[i].x, acc[j][i]);
                    acc[j][i] = fma2(xv.y, qv[i].y, acc[j][i]);
                }
            }
        }
        __syncthreads();

        // end of an l-half: fold acc -> scores, reset acc
        if ((it & 7) == 7) {
            const float scale = 0.03125f;
#pragma unroll
            for (int j = 0; j < 8; ++j)
#pragma unroll
                for (int i = 0; i < 4; ++i) {
                    float2 f = unpack2(acc[j][i]);
                    float s = f.x + f.y;
                    s += __shfl_xor_sync(0xffffffffu, s, 1);
                    s += __shfl_xor_sync(0xffffffffu, s, 2);
                    s += __shfl_xor_sync(0xffffffffu, s, 4);
                    if (cg == 0) {
                        const int l = h * 64 + w * 8 + j;
                        const int k = kg * 4 + i;
                        s_s[k * CHUNK + l] = mask_s[l] ? (s * scale) : NEG_INF;
                    }
                    acc[j][i] = 0ULL;
                }
        }
    }
    __syncthreads();

    // ---------------- Phase B: 8 warps x 2 k each ----------------
#pragma unroll
    for (int kk = 0; kk < 2; ++kk) {
        const int k = w + kk * 8;
        float v0 = s_s[k * CHUNK + lane];
        float v1 = s_s[k * CHUNK + lane + 32];
        float v2 = s_s[k * CHUNK + lane + 64];
        float v3 = s_s[k * CHUNK + lane + 96];
        float m = fmaxf(fmaxf(v0, v1), fmaxf(v2, v3));
#pragma unroll
        for (int off = 16; off; off >>= 1)
            m = fmaxf(m, __shfl_xor_sync(0xffffffffu, m, off));
        float e0, e1, e2, e3;
        if (m == NEG_INF) {
            e0 = e1 = e2 = e3 = 0.f;
        } else {
            e0 = __expf(v0 - m); e1 = __expf(v1 - m);
            e2 = __expf(v2 - m); e3 = __expf(v3 - m);
        }
        float d = e0 + e1 + e2 + e3;
#pragma unroll
        for (int off = 16; off; off >>= 1)
            d += __shfl_xor_sync(0xffffffffu, d, off);
        float* w2f = (float*)(smem + W2OFF);
        {
            int l = lane;
            w2f[(l >> 1) * 32 + k * 2 + (l & 1)] = e0;
            l = lane + 32;
            w2f[(l >> 1) * 32 + k * 2 + (l & 1)] = e1;
            l = lane + 64;
            w2f[(l >> 1) * 32 + k * 2 + (l & 1)] = e2;
            l = lane + 96;
            w2f[(l >> 1) * 32 + k * 2 + (l & 1)] = e3;
        }
        if (lane == 0) {
            g_m[(b * NSPLIT + split) * Kn + k] = m;
            g_d[(b * NSPLIT + split) * Kn + k] = d;
        }
    }
    __syncthreads();

    // -------- Phase C: two c-halves, depth-4 LDG prefetch --------
    const ulonglong2* w2v = (const ulonglong2*)(smem + W2OFF);
    float* ab = g_acc + ((size_t)(b * NSPLIT + split) * Kn) * Cn;
#pragma unroll
    for (int half = 0; half < 2; ++half) {
        const int c0 = half * 512 + tid * 2;
        ull a2[Kn][2];
#pragma unroll
        for (int k = 0; k < Kn; ++k) { a2[k][0] = 0ULL; a2[k][1] = 0ULL; }

        ull xb0[4], xb1[4];
#pragma unroll
        for (int i = 0; i < 4; ++i) {
            xb0[i] = *(const ull*)(xbase + (size_t)(2 * i) * Cn + c0);
            xb1[i] = *(const ull*)(xbase + (size_t)(2 * i + 1) * Cn + c0);
        }

#pragma unroll 4
        for (int lp = 0; lp < 64; ++lp) {
            const int sl = lp & 3;
            float2 fa = unpack2(xb0[sl]);
            float2 fb = unpack2(xb1[sl]);
            ull v0 = pack2(fa.x, fb.x);
            ull v1 = pack2(fa.y, fb.y);
            if (lp < 60) {
                xb0[sl] = *(const ull*)(xbase + (size_t)(2 * (lp + 4)) * Cn + c0);
                xb1[sl] = *(const ull*)(xbase + (size_t)(2 * (lp + 4) + 1) * Cn + c0);
            }
#pragma unroll
            for (int kp = 0; kp < 8; ++kp) {
                ulonglong2 wp = w2v[lp * 8 + kp];
                a2[2 * kp][0]     = fma2(wp.x, v0, a2[2 * kp][0]);
                a2[2 * kp][1]     = fma2(wp.x, v1, a2[2 * kp][1]);
                a2[2 * kp + 1][0] = fma2(wp.y, v0, a2[2 * kp + 1][0]);
                a2[2 * kp + 1][1] = fma2(wp.y, v1, a2[2 * kp + 1][1]);
            }
        }
#pragma unroll
        for (int k = 0; k < Kn; ++k) {
            float2 r0 = unpack2(a2[k][0]);
            float2 r1 = unpack2(a2[k][1]);
            float2 o;
            o.x = r0.x + r0.y;
            o.y = r1.x + r1.y;
            *(float2*)(ab + (size_t)k * Cn + c0) = o;
        }
    }
}

// ---------------- Kernel 2: LSE merge ----------------
extern "C" __global__ void __launch_bounds__(128)
pool_reduce_kernel(float* __restrict__ out) {
    const int bk = blockIdx.x >> 2;
    const int b = bk >> 4;
    const int k = bk & 15;
    const int cq = blockIdx.x & 3;
    const int tid = threadIdx.x;

    __shared__ float coef[NSPLIT];
    if (tid < NSPLIT) {
        float m = g_m[(b * NSPLIT + tid) * Kn + k];
        float d = g_d[(b * NSPLIT + tid) * Kn + k];
        float M = m;
#pragma unroll
        for (int off = 16; off; off >>= 1)
            M = fmaxf(M, __shfl_xor_sync(0xffffffffu, M, off));
        float t = (m == NEG_INF) ? 0.f : d * __expf(m - M);
        float D = t;
#pragma unroll
        for (int off = 16; off; off >>= 1)
            D += __shfl_xor_sync(0xffffffffu, D, off);
        float c = 0.f;
        if (M != NEG_INF && D > 0.f)
            c = __expf(m - M) / D;
        coef[tid] = c;
    }
    __syncthreads();

    const int c0 = cq * 256 + tid * 2;
    ull o = 0ULL;
    const float* accb = g_acc + ((size_t)b * NSPLIT * Kn + k) * Cn;
#pragma unroll
    for (int s = 0; s < NSPLIT; ++s) {
        ull cs = pack2(coef[s], coef[s]);
        ull a = *(const ull*)(accb + (size_t)s * Kn * Cn + c0);
        o = fma2(cs, a, o);
    }
    *(ull*)(out + ((size_t)(b * Kn + k)) * Cn + c0) = o;
}

// ---------------- instrumentation: one dummy between P and R ----------------
extern "C" __global__ void dummy_pad_kernel() {}

extern "C" void kernel_launch(void* const* d_in, const int* in_sizes, int n_in,
                              void* d_out, int out_size) {
    const float* x  = (const float*)d_in[0];
    const int* mask = (const int*)d_in[1];
    const float* q  = (const float*)d_in[2];
    float* out      = (float*)d_out;

    cudaFuncSetAttribute(pool_partial_kernel,
                         cudaFuncAttributeMaxDynamicSharedMemorySize, SMEM_TOTAL);
    pool_partial_kernel<<<Bn * NSPLIT, THREADS, SMEM_TOTAL>>>(x, mask, q);
    dummy_pad_kernel<<<1, 32>>>();
    pool_reduce_kernel<<<Bn * Kn * 4, 128>>>(out);
}

// round 14
// speedup vs baseline: 1.0117x; 1.0117x over previous
#include <cuda_runtime.h>
#include <math.h>

#define Bn 16
#define Ln 4096
#define Cn 1024
#define Kn 16
#define NSPLIT 32
#define CHUNK 128
#define THREADS 512
#define TC 128
#define NTILE 8
#define QSTRIDE 132
#define NEG_INF (__int_as_float(0xff800000))

typedef unsigned long long ull;

__device__ float g_acc[(size_t)Bn * NSPLIT * Kn * Cn];
__device__ float g_m[Bn * NSPLIT * Kn];
__device__ float g_d[Bn * NSPLIT * Kn];

__device__ __forceinline__ ull fma2(ull a, ull b, ull c) {
    ull d;
    asm("fma.rn.f32x2 %0, %1, %2, %3;" : "=l"(d) : "l"(a), "l"(b), "l"(c));
    return d;
}
__device__ __forceinline__ float2 unpack2(ull v) {
    float2 f;
    f.x = __uint_as_float((unsigned)(v & 0xffffffffULL));
    f.y = __uint_as_float((unsigned)(v >> 32));
    return f;
}
__device__ __forceinline__ ull pack2(float a, float b) {
    ull v;
    asm("mov.b64 %0, {%1, %2};" : "=l"(v) : "f"(a), "f"(b));
    return v;
}
__device__ __forceinline__ void cp_async16(unsigned int smem, const void* g) {
    asm volatile("cp.async.cg.shared.global [%0], [%1], 16;" :: "r"(smem), "l"(g));
}
__device__ __forceinline__ void cp_commit() {
    asm volatile("cp.async.commit_group;");
}
template <int N>
__device__ __forceinline__ void cp_wait() {
    asm volatile("cp.async.wait_group %0;" :: "n"(N) : "memory");
}

// SMEM byte offsets
#define XS0   0
#define XS1   65536
#define QS0   131072
#define QS1   (131072 + 8448)
#define SSOFF (131072 + 16896)
#define W2OFF (SSOFF + Kn * CHUNK * 4)
#define MKOFF (W2OFF + 64 * Kn * 8)
#define SMEM_TOTAL (MKOFF + CHUNK * 4)

extern "C" __global__ void __launch_bounds__(THREADS, 1)
pool_partial_kernel(const float* __restrict__ x,
                    const int* __restrict__ mask,
                    const float* __restrict__ q) {
    extern __shared__ char smem[];
    unsigned int smem_u32 = (unsigned int)__cvta_generic_to_shared(smem);
    float* s_s = (float*)(smem + SSOFF);
    int* mask_s = (int*)(smem + MKOFF);

    const int tid = threadIdx.x;
    const int w = tid >> 5;
    const int lane = tid & 31;
    const int cg = lane & 7;
    const int kg = lane >> 3;
    const int b = blockIdx.x / NSPLIT;
    const int split = blockIdx.x % NSPLIT;
    const int l0 = split * CHUNK;
    const float* xbase = x + ((size_t)b * Ln + l0) * Cn;

    // ---- prefetch tile 0 (x + q) ----
    {
        unsigned int xd = smem_u32 + XS0;
#pragma unroll
        for (int r = 0; r < 8; ++r) {
            int id = tid + THREADS * r;
            int row = id >> 5, c4 = id & 31;
            cp_async16(xd + row * 512 + c4 * 16,
                       xbase + (size_t)row * Cn + c4 * 4);
        }
        int qrow = tid >> 5, qc4 = tid & 31;
        cp_async16(smem_u32 + QS0 + qrow * (QSTRIDE * 4) + qc4 * 16,
                   q + qrow * Cn + qc4 * 4);
        cp_commit();
    }
    if (tid < CHUNK) mask_s[tid] = mask[b * Ln + l0 + tid];

    ull acc[8][4];
#pragma unroll
    for (int a = 0; a < 8; ++a)
#pragma unroll
        for (int i = 0; i < 4; ++i) acc[a][i] = 0ULL;

    // ---------------- Phase A ----------------
    for (int t = 0; t < NTILE; ++t) {
        if (t < NTILE - 1) {
            const int tn = t + 1;
            unsigned int xd = smem_u32 + ((tn & 1) ? XS1 : XS0);
#pragma unroll
            for (int r = 0; r < 8; ++r) {
                int id = tid + THREADS * r;
                int row = id >> 5, c4 = id & 31;
                cp_async16(xd + row * 512 + c4 * 16,
                           xbase + (size_t)row * Cn + tn * TC + c4 * 4);
            }
            int qrow = tid >> 5, qc4 = tid & 31;
            cp_async16(smem_u32 + ((tn & 1) ? QS1 : QS0) + qrow * (QSTRIDE * 4) + qc4 * 16,
                       q + qrow * Cn + tn * TC + qc4 * 4);
            cp_commit();
            cp_wait<1>();
        } else {
            cp_wait<0>();
        }
        __syncthreads();

        const float* xs = (const float*)(smem + ((t & 1) ? XS1 : XS0));
        const float* qs = (const float*)(smem + ((t & 1) ? QS1 : QS0));

#pragma unroll
        for (int quad = 0; quad < 4; ++quad) {
            const int cof = cg * 4 + quad * 32;
            ulonglong2 qv[4];
#pragma unroll
            for (int i = 0; i < 4; ++i)
                qv[i] = *(const ulonglong2*)(qs + (kg * 4 + i) * QSTRIDE + cof);
#pragma unroll
            for (int j = 0; j < 8; ++j) {
                ulonglong2 xv = *(const ulonglong2*)(xs + (w * 8 + j) * TC + cof);
                // RAW-break: all .x FMAs first, then all .y (reuse distance 4 instrs)
#pragma unroll
                for (int i = 0; i < 4; ++i)
                    acc[j][i] = fma2(xv.x, qv[i].x, acc[j][i]);
#pragma unroll
                for (int i = 0; i < 4; ++i)
                    acc[j][i] = fma2(xv.y, qv[i].y, acc[j][i]);
            }
        }
        __syncthreads();
    }

    // ---- fold + 3-shfl cg reduction + masked write ----
    {
        const float scale = 0.03125f;
#pragma unroll
        for (int j = 0; j < 8; ++j)
#pragma unroll
            for (int i = 0; i < 4; ++i) {
                float2 f = unpack2(acc[j][i]);
                float s = f.x + f.y;
                s += __shfl_xor_sync(0xffffffffu, s, 1);
                s += __shfl_xor_sync(0xffffffffu, s, 2);
                s += __shfl_xor_sync(0xffffffffu, s, 4);
                if (cg == 0) {
                    const int l = w * 8 + j;
                    const int k = kg * 4 + i;
                    s_s[k * CHUNK + l] = mask_s[l] ? (s * scale) : NEG_INF;
                }
            }
    }
    __syncthreads();

    // ---------------- Phase B ----------------
    {
        const int k = w;
        float v0 = s_s[k * CHUNK + lane];
        float v1 = s_s[k * CHUNK + lane + 32];
        float v2 = s_s[k * CHUNK + lane + 64];
        float v3 = s_s[k * CHUNK + lane + 96];
        float m = fmaxf(fmaxf(v0, v1), fmaxf(v2, v3));
#pragma unroll
        for (int off = 16; off; off >>= 1)
            m = fmaxf(m, __shfl_xor_sync(0xffffffffu, m, off));
        float e0, e1, e2, e3;
        if (m == NEG_INF) {
            e0 = e1 = e2 = e3 = 0.f;
        } else {
            e0 = __expf(v0 - m); e1 = __expf(v1 - m);
            e2 = __expf(v2 - m); e3 = __expf(v3 - m);
        }
        float d = e0 + e1 + e2 + e3;
#pragma unroll
        for (int off = 16; off; off >>= 1)
            d += __shfl_xor_sync(0xffffffffu, d, off);
        float* w2f = (float*)(smem + W2OFF);
        {
            int l = lane;
            w2f[(l >> 1) * 32 + k * 2 + (l & 1)] = e0;
            l = lane + 32;
            w2f[(l >> 1) * 32 + k * 2 + (l & 1)] = e1;
            l = lane + 64;
            w2f[(l >> 1) * 32 + k * 2 + (l & 1)] = e2;
            l = lane + 96;
            w2f[(l >> 1) * 32 + k * 2 + (l & 1)] = e3;
        }
        if (lane == 0) {
            g_m[(b * NSPLIT + split) * Kn + k] = m;
            g_d[(b * NSPLIT + split) * Kn + k] = d;
        }
    }
    __syncthreads();

    // -------- Phase C: depth-4 LDG prefetch --------
    {
        const int c0 = tid * 2;
        const ulonglong2* w2v = (const ulonglong2*)(smem + W2OFF);
        ull a2[Kn][2];
#pragma unroll
        for (int k = 0; k < Kn; ++k) { a2[k][0] = 0ULL; a2[k][1] = 0ULL; }

        ull xb0[4], xb1[4];
#pragma unroll
        for (int i = 0; i < 4; ++i) {
            xb0[i] = *(const ull*)(xbase + (size_t)(2 * i) * Cn + c0);
            xb1[i] = *(const ull*)(xbase + (size_t)(2 * i + 1) * Cn + c0);
        }

#pragma unroll 4
        for (int lp = 0; lp < 64; ++lp) {
            const int sl = lp & 3;
            float2 fa = unpack2(xb0[sl]);
            float2 fb = unpack2(xb1[sl]);
            ull v0 = pack2(fa.x, fb.x);
            ull v1 = pack2(fa.y, fb.y);
            if (lp < 60) {
                xb0[sl] = *(const ull*)(xbase + (size_t)(2 * (lp + 4)) * Cn + c0);
                xb1[sl] = *(const ull*)(xbase + (size_t)(2 * (lp + 4) + 1) * Cn + c0);
            }
#pragma unroll
            for (int kp = 0; kp < 8; ++kp) {
                ulonglong2 wp = w2v[lp * 8 + kp];
                a2[2 * kp][0]     = fma2(wp.x, v0, a2[2 * kp][0]);
                a2[2 * kp][1]     = fma2(wp.x, v1, a2[2 * kp][1]);
                a2[2 * kp + 1][0] = fma2(wp.y, v0, a2[2 * kp + 1][0]);
                a2[2 * kp + 1][1] = fma2(wp.y, v1, a2[2 * kp + 1][1]);
            }
        }
        float* ab = g_acc + ((size_t)(b * NSPLIT + split) * Kn) * Cn;
#pragma unroll
        for (int k = 0; k < Kn; ++k) {
            float2 r0 = unpack2(a2[k][0]);
            float2 r1 = unpack2(a2[k][1]);
            float2 o;
            o.x = r0.x + r0.y;
            o.y = r1.x + r1.y;
            *(float2*)(ab + (size_t)k * Cn + c0) = o;
        }
    }
}

// ---------------- Kernel 2: LSE merge (float4, 512 blocks) ----------------
extern "C" __global__ void __launch_bounds__(128)
pool_reduce_kernel(float* __restrict__ out) {
    const int bk = blockIdx.x >> 1;
    const int b = bk >> 4;
    const int k = bk & 15;
    const int ch = blockIdx.x & 1;
    const int tid = threadIdx.x;

    __shared__ float coef[NSPLIT];
    if (tid < NSPLIT) {
        float m = g_m[(b * NSPLIT + tid) * Kn + k];
        float d = g_d[(b * NSPLIT + tid) * Kn + k];
        float M = m;
#pragma unroll
        for (int off = 16; off; off >>= 1)
            M = fmaxf(M, __shfl_xor_sync(0xffffffffu, M, off));
        float t = (m == NEG_INF) ? 0.f : d * __expf(m - M);
        float D = t;
#pragma unroll
        for (int off = 16; off; off >>= 1)
            D += __shfl_xor_sync(0xffffffffu, D, off);
        float c = 0.f;
        if (M != NEG_INF && D > 0.f)
            c = __expf(m - M) / D;
        coef[tid] = c;
    }
    __syncthreads();

    const int c0 = ch * 512 + tid * 4;
    ull o0 = 0ULL, o1 = 0ULL;
    const float* accb = g_acc + ((size_t)b * NSPLIT * Kn + k) * Cn;
#pragma unroll
    for (int s = 0; s < NSPLIT; ++s) {
        ull cs = pack2(coef[s], coef[s]);
        ulonglong2 a = *(const ulonglong2*)(accb + (size_t)s * Kn * Cn + c0);
        o0 = fma2(cs, a.x, o0);
        o1 = fma2(cs, a.y, o1);
    }
    ulonglong2 ov; ov.x = o0; ov.y = o1;
    *(ulonglong2*)(out + ((size_t)(b * Kn + k)) * Cn + c0) = ov;
}

extern "C" void kernel_launch(void* const* d_in, const int* in_sizes, int n_in,
                              void* d_out, int out_size) {
    const float* x  = (const float*)d_in[0];
    const int* mask = (const int*)d_in[1];
    const float* q  = (const float*)d_in[2];
    float* out      = (float*)d_out;

    cudaFuncSetAttribute(pool_partial_kernel,
                         cudaFuncAttributeMaxDynamicSharedMemorySize, SMEM_TOTAL);
    pool_partial_kernel<<<Bn * NSPLIT, THREADS, SMEM_TOTAL>>>(x, mask, q);
    pool_reduce_kernel<<<Bn * Kn * 2, 128>>>(out);
}

// round 15
// speedup vs baseline: 1.0665x; 1.0541x over previous
#include <cuda_runtime.h>
#include <math.h>

#define Bn 16
#define Ln 4096
#define Cn 1024
#define Kn 16
#define NSPLIT 64
#define CHUNK 64
#define THREADS 256
#define TC 128
#define NTILE 8
#define QSTRIDE 132
#define NEG_INF (__int_as_float(0xff800000))

typedef unsigned long long ull;

__device__ float g_acc[(size_t)Bn * NSPLIT * Kn * Cn];   // 64MB partials
__device__ float g_m[Bn * NSPLIT * Kn];
__device__ float g_d[Bn * NSPLIT * Kn];

__device__ __forceinline__ ull fma2(ull a, ull b, ull c) {
    ull d;
    asm("fma.rn.f32x2 %0, %1, %2, %3;" : "=l"(d) : "l"(a), "l"(b), "l"(c));
    return d;
}
__device__ __forceinline__ float2 unpack2(ull v) {
    float2 f;
    f.x = __uint_as_float((unsigned)(v & 0xffffffffULL));
    f.y = __uint_as_float((unsigned)(v >> 32));
    return f;
}
__device__ __forceinline__ ull pack2(float a, float b) {
    ull v;
    asm("mov.b64 %0, {%1, %2};" : "=l"(v) : "f"(a), "f"(b));
    return v;
}
__device__ __forceinline__ void cp_async16(unsigned int smem, const void* g) {
    asm volatile("cp.async.cg.shared.global [%0], [%1], 16;" :: "r"(smem), "l"(g));
}
__device__ __forceinline__ void cp_commit() {
    asm volatile("cp.async.commit_group;");
}
template <int N>
__device__ __forceinline__ void cp_wait() {
    asm volatile("cp.async.wait_group %0;" :: "n"(N) : "memory");
}

// SMEM byte offsets (total 90880 -> 2 blocks/SM)
#define XS0   0                         // 64 l x 128 c fp32 = 32KB
#define XS1   32768
#define QS0   65536                     // 16 k x 132 floats = 8448B
#define QS1   (65536 + 8448)
#define SSOFF 82432                     // scores [16 k][64 l] = 4KB
#define W2OFF 86528                     // weights [32 lp][16 k][2] floats = 4KB
#define MKOFF 90624                     // mask [64] int
#define SMEM_TOTAL 90880

extern "C" __global__ void __launch_bounds__(THREADS, 2)
pool_partial_kernel(const float* __restrict__ x,
                    const int* __restrict__ mask,
                    const float* __restrict__ q) {
    extern __shared__ char smem[];
    unsigned int smem_u32 = (unsigned int)__cvta_generic_to_shared(smem);
    float* s_s = (float*)(smem + SSOFF);
    int* mask_s = (int*)(smem + MKOFF);

    const int tid = threadIdx.x;
    const int w = tid >> 5;             // 8 warps, warp owns 8 l
    const int lane = tid & 31;
    const int cg = lane & 7;
    const int kg = lane >> 3;
    const int b = blockIdx.x / NSPLIT;
    const int split = blockIdx.x % NSPLIT;
    const int l0 = split * CHUNK;
    const float* xbase = x + ((size_t)b * Ln + l0) * Cn;

    // ---- prefetch tile 0 (x 64x128 + q tile 0) ----
    {
        unsigned int xd = smem_u32 + XS0;
#pragma unroll
        for (int r = 0; r < 8; ++r) {
            int id = tid + THREADS * r;          // 2048 float4
            int row = id >> 5, c4 = id & 31;
            cp_async16(xd + row * 512 + c4 * 16,
                       xbase + (size_t)row * Cn + c4 * 4);
        }
#pragma unroll
        for (int r = 0; r < 2; ++r) {
            int id = tid + THREADS * r;          // 512 float4
            int qrow = id >> 5, qc4 = id & 31;
            cp_async16(smem_u32 + QS0 + qrow * (QSTRIDE * 4) + qc4 * 16,
                       q + qrow * Cn + qc4 * 4);
        }
        cp_commit();
    }
    if (tid < CHUNK) mask_s[tid] = mask[b * Ln + l0 + tid];

    ull acc[8][4];
#pragma unroll
    for (int a = 0; a < 8; ++a)
#pragma unroll
        for (int i = 0; i < 4; ++i) acc[a][i] = 0ULL;

    // ---------------- Phase A: 8 c-tiles of 128 ----------------
    for (int t = 0; t < NTILE; ++t) {
        if (t < NTILE - 1) {
            const int tn = t + 1;
            unsigned int xd = smem_u32 + ((tn & 1) ? XS1 : XS0);
#pragma unroll
            for (int r = 0; r < 8; ++r) {
                int id = tid + THREADS * r;
                int row = id >> 5, c4 = id & 31;
                cp_async16(xd + row * 512 + c4 * 16,
                           xbase + (size_t)row * Cn + tn * TC + c4 * 4);
            }
#pragma unroll
            for (int r = 0; r < 2; ++r) {
                int id = tid + THREADS * r;
                int qrow = id >> 5, qc4 = id & 31;
                cp_async16(smem_u32 + ((tn & 1) ? QS1 : QS0) + qrow * (QSTRIDE * 4) + qc4 * 16,
                           q + qrow * Cn + tn * TC + qc4 * 4);
            }
            cp_commit();
            cp_wait<1>();
        } else {
            cp_wait<0>();
        }
        __syncthreads();

        const float* xs = (const float*)(smem + ((t & 1) ? XS1 : XS0));
        const float* qs = (const float*)(smem + ((t & 1) ? QS1 : QS0));

#pragma unroll
        for (int quad = 0; quad < 4; ++quad) {
            const int cof = cg * 4 + quad * 32;
            ulonglong2 qv[4];
#pragma unroll
            for (int i = 0; i < 4; ++i)
                qv[i] = *(const ulonglong2*)(qs + (kg * 4 + i) * QSTRIDE + cof);
#pragma unroll
            for (int j = 0; j < 8; ++j) {
                ulonglong2 xv = *(const ulonglong2*)(xs + (w * 8 + j) * TC + cof);
#pragma unroll
                for (int i = 0; i < 4; ++i) {
                    acc[j][i] = fma2(xv.x, qv[i].x, acc[j][i]);
                    acc[j][i] = fma2(xv.y, qv[i].y, acc[j][i]);
                }
            }
        }
        __syncthreads();
    }

    // ---- fold + 3-shfl cg reduction + masked write to scores ----
    {
        const float scale = 0.03125f;
#pragma unroll
        for (int j = 0; j < 8; ++j)
#pragma unroll
            for (int i = 0; i < 4; ++i) {
                float2 f = unpack2(acc[j][i]);
                float s = f.x + f.y;
                s += __shfl_xor_sync(0xffffffffu, s, 1);
                s += __shfl_xor_sync(0xffffffffu, s, 2);
                s += __shfl_xor_sync(0xffffffffu, s, 4);
                if (cg == 0) {
                    const int l = w * 8 + j;
                    const int k = kg * 4 + i;
                    s_s[k * CHUNK + l] = mask_s[l] ? (s * scale) : NEG_INF;
                }
            }
    }
    __syncthreads();

    // ---------------- Phase B: 8 warps x 2 k each ----------------
#pragma unroll
    for (int kk = 0; kk < 2; ++kk) {
        const int k = w + kk * 8;
        float v0 = s_s[k * CHUNK + lane];
        float v1 = s_s[k * CHUNK + lane + 32];
        float m = fmaxf(v0, v1);
#pragma unroll
        for (int off = 16; off; off >>= 1)
            m = fmaxf(m, __shfl_xor_sync(0xffffffffu, m, off));
        float e0, e1;
        if (m == NEG_INF) {
            e0 = e1 = 0.f;
        } else {
            e0 = __expf(v0 - m);
            e1 = __expf(v1 - m);
        }
        float d = e0 + e1;
#pragma unroll
        for (int off = 16; off; off >>= 1)
            d += __shfl_xor_sync(0xffffffffu, d, off);
        float* w2f = (float*)(smem + W2OFF);
        {
            int l = lane;
            w2f[(l >> 1) * 32 + k * 2 + (l & 1)] = e0;
            l = lane + 32;
            w2f[(l >> 1) * 32 + k * 2 + (l & 1)] = e1;
        }
        if (lane == 0) {
            g_m[(b * NSPLIT + split) * Kn + k] = m;
            g_d[(b * NSPLIT + split) * Kn + k] = d;
        }
    }
    __syncthreads();

    // -------- Phase C: 2 c-half passes, 32 l-pairs, depth-4 LDG prefetch --------
    const ulonglong2* w2v = (const ulonglong2*)(smem + W2OFF);
    float* ab = g_acc + ((size_t)(b * NSPLIT + split) * Kn) * Cn;
#pragma unroll
    for (int half = 0; half < 2; ++half) {
        const int c0 = half * 512 + tid * 2;
        ull a2[Kn][2];
#pragma unroll
        for (int k = 0; k < Kn; ++k) { a2[k][0] = 0ULL; a2[k][1] = 0ULL; }

        ull xb0[4], xb1[4];
#pragma unroll
        for (int i = 0; i < 4; ++i) {
            xb0[i] = *(const ull*)(xbase + (size_t)(2 * i) * Cn + c0);
            xb1[i] = *(const ull*)(xbase + (size_t)(2 * i + 1) * Cn + c0);
        }

#pragma unroll 4
        for (int lp = 0; lp < 32; ++lp) {
            const int sl = lp & 3;
            float2 fa = unpack2(xb0[sl]);
            float2 fb = unpack2(xb1[sl]);
            ull v0 = pack2(fa.x, fb.x);
            ull v1 = pack2(fa.y, fb.y);
            if (lp < 28) {
                xb0[sl] = *(const ull*)(xbase + (size_t)(2 * (lp + 4)) * Cn + c0);
                xb1[sl] = *(const ull*)(xbase + (size_t)(2 * (lp + 4) + 1) * Cn + c0);
            }
#pragma unroll
            for (int kp = 0; kp < 8; ++kp) {
                ulonglong2 wp = w2v[lp * 8 + kp];
                a2[2 * kp][0]     = fma2(wp.x, v0, a2[2 * kp][0]);
                a2[2 * kp][1]     = fma2(wp.x, v1, a2[2 * kp][1]);
                a2[2 * kp + 1][0] = fma2(wp.y, v0, a2[2 * kp + 1][0]);
                a2[2 * kp + 1][1] = fma2(wp.y, v1, a2[2 * kp + 1][1]);
            }
        }
#pragma unroll
        for (int k = 0; k < Kn; ++k) {
            float2 r0 = unpack2(a2[k][0]);
            float2 r1 = unpack2(a2[k][1]);
            float2 o;
            o.x = r0.x + r0.y;
            o.y = r1.x + r1.y;
            *(float2*)(ab + (size_t)k * Cn + c0) = o;
        }
    }
}

// ---------------- Kernel 2: LSE merge over 64 splits (float4) ----------------
extern "C" __global__ void __launch_bounds__(128)
pool_reduce_kernel(float* __restrict__ out) {
    const int bk = blockIdx.x >> 1;
    const int b = bk >> 4;
    const int k = bk & 15;
    const int ch = blockIdx.x & 1;
    const int tid = threadIdx.x;

    __shared__ float coef[NSPLIT];
    if (tid < 32) {
        float ma = g_m[(b * NSPLIT + tid) * Kn + k];
        float mb = g_m[(b * NSPLIT + tid + 32) * Kn + k];
        float da = g_d[(b * NSPLIT + tid) * Kn + k];
        float db = g_d[(b * NSPLIT + tid + 32) * Kn + k];
        float M = fmaxf(ma, mb);
#pragma unroll
        for (int off = 16; off; off >>= 1)
            M = fmaxf(M, __shfl_xor_sync(0xffffffffu, M, off));
        float ta = (ma == NEG_INF) ? 0.f : da * __expf(ma - M);
        float tb = (mb == NEG_INF) ? 0.f : db * __expf(mb - M);
        float D = ta + tb;
#pragma unroll
        for (int off = 16; off; off >>= 1)
            D += __shfl_xor_sync(0xffffffffu, D, off);
        float ca = 0.f, cb = 0.f;
        if (M != NEG_INF && D > 0.f) {
            ca = __expf(ma - M) / D;   // ma==-inf -> 0
            cb = __expf(mb - M) / D;
        }
        coef[tid] = ca;
        coef[tid + 32] = cb;
    }
    __syncthreads();

    const int c0 = ch * 512 + tid * 4;
    ull o0 = 0ULL, o1 = 0ULL;
    const float* accb = g_acc + ((size_t)b * NSPLIT * Kn + k) * Cn;
#pragma unroll 8
    for (int s = 0; s < NSPLIT; ++s) {
        ull cs = pack2(coef[s], coef[s]);
        ulonglong2 a = *(const ulonglong2*)(accb + (size_t)s * Kn * Cn + c0);
        o0 = fma2(cs, a.x, o0);
        o1 = fma2(cs, a.y, o1);
    }
    ulonglong2 ov; ov.x = o0; ov.y = o1;
    *(ulonglong2*)(out + ((size_t)(b * Kn + k)) * Cn + c0) = ov;
}

extern "C" void kernel_launch(void* const* d_in, const int* in_sizes, int n_in,
                              void* d_out, int out_size) {
    const float* x  = (const float*)d_in[0];
    const int* mask = (const int*)d_in[1];
    const float* q  = (const float*)d_in[2];
    float* out      = (float*)d_out;

    cudaFuncSetAttribute(pool_partial_kernel,
                         cudaFuncAttributeMaxDynamicSharedMemorySize, SMEM_TOTAL);
    pool_partial_kernel<<<Bn * NSPLIT, THREADS, SMEM_TOTAL>>>(x, mask, q);
    pool_reduce_kernel<<<Bn * Kn * 2, 128>>>(out);
}

// round 16
// speedup vs baseline: 1.1117x; 1.0424x over previous
#include <cuda_runtime.h>
#include <math.h>

#define Bn 16
#define Ln 4096
#define Cn 1024
#define Kn 16
#define NSPLIT 64
#define CHUNK 64
#define THREADS 256
#define TC 128
#define NTILE 8
#define QSTRIDE 132
#define NEG_INF (__int_as_float(0xff800000))

typedef unsigned long long ull;

__device__ float g_acc[(size_t)Bn * NSPLIT * Kn * Cn];   // 64MB partials
__device__ float g_m[Bn * NSPLIT * Kn];
__device__ float g_d[Bn * NSPLIT * Kn];

__device__ __forceinline__ ull fma2(ull a, ull b, ull c) {
    ull d;
    asm("fma.rn.f32x2 %0, %1, %2, %3;" : "=l"(d) : "l"(a), "l"(b), "l"(c));
    return d;
}
__device__ __forceinline__ float2 unpack2(ull v) {
    float2 f;
    f.x = __uint_as_float((unsigned)(v & 0xffffffffULL));
    f.y = __uint_as_float((unsigned)(v >> 32));
    return f;
}
__device__ __forceinline__ ull pack2(float a, float b) {
    ull v;
    asm("mov.b64 %0, {%1, %2};" : "=l"(v) : "f"(a), "f"(b));
    return v;
}
__device__ __forceinline__ void cp_async16(unsigned int smem, const void* g) {
    asm volatile("cp.async.cg.shared.global [%0], [%1], 16;" :: "r"(smem), "l"(g));
}
__device__ __forceinline__ void cp_commit() {
    asm volatile("cp.async.commit_group;");
}
template <int N>
__device__ __forceinline__ void cp_wait() {
    asm volatile("cp.async.wait_group %0;" :: "n"(N) : "memory");
}

// SMEM byte offsets (total 90880 -> 2 blocks/SM)
#define XS0   0
#define XS1   32768
#define QS0   65536
#define QS1   (65536 + 8448)
#define SSOFF 82432
#define W2OFF 86528
#define MKOFF 90624
#define SMEM_TOTAL 90880

extern "C" __global__ void __launch_bounds__(THREADS, 2)
pool_partial_kernel(const float* __restrict__ x,
                    const int* __restrict__ mask,
                    const float* __restrict__ q) {
    extern __shared__ char smem[];
    unsigned int smem_u32 = (unsigned int)__cvta_generic_to_shared(smem);
    float* s_s = (float*)(smem + SSOFF);
    int* mask_s = (int*)(smem + MKOFF);

    const int tid = threadIdx.x;
    const int w = tid >> 5;
    const int lane = tid & 31;
    const int cg = lane & 7;
    const int kg = lane >> 3;
    const int b = blockIdx.x / NSPLIT;
    const int split = blockIdx.x % NSPLIT;
    const int l0 = split * CHUNK;
    const float* xbase = x + ((size_t)b * Ln + l0) * Cn;

    // ---- prefetch tile 0 (x 64x128 + q tile 0) ----
    {
        unsigned int xd = smem_u32 + XS0;
#pragma unroll
        for (int r = 0; r < 8; ++r) {
            int id = tid + THREADS * r;
            int row = id >> 5, c4 = id & 31;
            cp_async16(xd + row * 512 + c4 * 16,
                       xbase + (size_t)row * Cn + c4 * 4);
        }
#pragma unroll
        for (int r = 0; r < 2; ++r) {
            int id = tid + THREADS * r;
            int qrow = id >> 5, qc4 = id & 31;
            cp_async16(smem_u32 + QS0 + qrow * (QSTRIDE * 4) + qc4 * 16,
                       q + qrow * Cn + qc4 * 4);
        }
        cp_commit();
    }
    if (tid < CHUNK) mask_s[tid] = mask[b * Ln + l0 + tid];

    ull acc[8][4];
#pragma unroll
    for (int a = 0; a < 8; ++a)
#pragma unroll
        for (int i = 0; i < 4; ++i) acc[a][i] = 0ULL;

    // ---------------- Phase A: 8 c-tiles of 128 ----------------
    for (int t = 0; t < NTILE; ++t) {
        if (t < NTILE - 1) {
            const int tn = t + 1;
            unsigned int xd = smem_u32 + ((tn & 1) ? XS1 : XS0);
#pragma unroll
            for (int r = 0; r < 8; ++r) {
                int id = tid + THREADS * r;
                int row = id >> 5, c4 = id & 31;
                cp_async16(xd + row * 512 + c4 * 16,
                           xbase + (size_t)row * Cn + tn * TC + c4 * 4);
            }
#pragma unroll
            for (int r = 0; r < 2; ++r) {
                int id = tid + THREADS * r;
                int qrow = id >> 5, qc4 = id & 31;
                cp_async16(smem_u32 + ((tn & 1) ? QS1 : QS0) + qrow * (QSTRIDE * 4) + qc4 * 16,
                           q + qrow * Cn + tn * TC + qc4 * 4);
            }
            cp_commit();
            cp_wait<1>();
        } else {
            cp_wait<0>();
        }
        __syncthreads();

        const float* xs = (const float*)(smem + ((t & 1) ? XS1 : XS0));
        const float* qs = (const float*)(smem + ((t & 1) ? QS1 : QS0));

#pragma unroll
        for (int quad = 0; quad < 4; ++quad) {
            const int cof = cg * 4 + quad * 32;
            ulonglong2 qv[4];
#pragma unroll
            for (int i = 0; i < 4; ++i)
                qv[i] = *(const ulonglong2*)(qs + (kg * 4 + i) * QSTRIDE + cof);
#pragma unroll
            for (int j = 0; j < 8; ++j) {
                ulonglong2 xv = *(const ulonglong2*)(xs + (w * 8 + j) * TC + cof);
#pragma unroll
                for (int i = 0; i < 4; ++i) {
                    acc[j][i] = fma2(xv.x, qv[i].x, acc[j][i]);
                    acc[j][i] = fma2(xv.y, qv[i].y, acc[j][i]);
                }
            }
        }
        __syncthreads();
    }

    // ---- fold + 3-shfl cg reduction + masked write ----
    {
        const float scale = 0.03125f;
#pragma unroll
        for (int j = 0; j < 8; ++j)
#pragma unroll
            for (int i = 0; i < 4; ++i) {
                float2 f = unpack2(acc[j][i]);
                float s = f.x + f.y;
                s += __shfl_xor_sync(0xffffffffu, s, 1);
                s += __shfl_xor_sync(0xffffffffu, s, 2);
                s += __shfl_xor_sync(0xffffffffu, s, 4);
                if (cg == 0) {
                    const int l = w * 8 + j;
                    const int k = kg * 4 + i;
                    s_s[k * CHUNK + l] = mask_s[l] ? (s * scale) : NEG_INF;
                }
            }
    }
    __syncthreads();

    // ---------------- Phase B: 8 warps x 2 k each ----------------
#pragma unroll
    for (int kk = 0; kk < 2; ++kk) {
        const int k = w + kk * 8;
        float v0 = s_s[k * CHUNK + lane];
        float v1 = s_s[k * CHUNK + lane + 32];
        float m = fmaxf(v0, v1);
#pragma unroll
        for (int off = 16; off; off >>= 1)
            m = fmaxf(m, __shfl_xor_sync(0xffffffffu, m, off));
        float e0, e1;
        if (m == NEG_INF) {
            e0 = e1 = 0.f;
        } else {
            e0 = __expf(v0 - m);
            e1 = __expf(v1 - m);
        }
        float d = e0 + e1;
#pragma unroll
        for (int off = 16; off; off >>= 1)
            d += __shfl_xor_sync(0xffffffffu, d, off);
        float* w2f = (float*)(smem + W2OFF);
        {
            int l = lane;
            w2f[(l >> 1) * 32 + k * 2 + (l & 1)] = e0;
            l = lane + 32;
            w2f[(l >> 1) * 32 + k * 2 + (l & 1)] = e1;
        }
        if (lane == 0) {
            g_m[(b * NSPLIT + split) * Kn + k] = m;
            g_d[(b * NSPLIT + split) * Kn + k] = d;
        }
    }
    __syncthreads();

    // -------- Phase C: 2 c-half passes, 32 l-pairs, depth-4 LDG prefetch --------
    const ulonglong2* w2v = (const ulonglong2*)(smem + W2OFF);
    float* ab = g_acc + ((size_t)(b * NSPLIT + split) * Kn) * Cn;
#pragma unroll
    for (int half = 0; half < 2; ++half) {
        const int c0 = half * 512 + tid * 2;
        ull a2[Kn][2];
#pragma unroll
        for (int k = 0; k < Kn; ++k) { a2[k][0] = 0ULL; a2[k][1] = 0ULL; }

        ull xb0[4], xb1[4];
#pragma unroll
        for (int i = 0; i < 4; ++i) {
            xb0[i] = *(const ull*)(xbase + (size_t)(2 * i) * Cn + c0);
            xb1[i] = *(const ull*)(xbase + (size_t)(2 * i + 1) * Cn + c0);
        }

#pragma unroll 4
        for (int lp = 0; lp < 32; ++lp) {
            const int sl = lp & 3;
            float2 fa = unpack2(xb0[sl]);
            float2 fb = unpack2(xb1[sl]);
            ull v0 = pack2(fa.x, fb.x);
            ull v1 = pack2(fa.y, fb.y);
            if (lp < 28) {
                xb0[sl] = *(const ull*)(xbase + (size_t)(2 * (lp + 4)) * Cn + c0);
                xb1[sl] = *(const ull*)(xbase + (size_t)(2 * (lp + 4) + 1) * Cn + c0);
            }
#pragma unroll
            for (int kp = 0; kp < 8; ++kp) {
                ulonglong2 wp = w2v[lp * 8 + kp];
                a2[2 * kp][0]     = fma2(wp.x, v0, a2[2 * kp][0]);
                a2[2 * kp][1]     = fma2(wp.x, v1, a2[2 * kp][1]);
                a2[2 * kp + 1][0] = fma2(wp.y, v0, a2[2 * kp + 1][0]);
                a2[2 * kp + 1][1] = fma2(wp.y, v1, a2[2 * kp + 1][1]);
            }
        }
#pragma unroll
        for (int k = 0; k < Kn; ++k) {
            float2 r0 = unpack2(a2[k][0]);
            float2 r1 = unpack2(a2[k][1]);
            float2 o;
            o.x = r0.x + r0.y;
            o.y = r1.x + r1.y;
            *(float2*)(ab + (size_t)k * Cn + c0) = o;
        }
    }
}

// ------- Kernel 2: LSE merge, 1024 blocks (b,k,c-quarter), float2/thread -------
extern "C" __global__ void __launch_bounds__(128)
pool_reduce_kernel(float* __restrict__ out) {
    const int bk = blockIdx.x >> 2;
    const int b = bk >> 4;
    const int k = bk & 15;
    const int cq = blockIdx.x & 3;
    const int tid = threadIdx.x;

    __shared__ float coef[NSPLIT];
    if (tid < 32) {
        float ma = g_m[(b * NSPLIT + tid) * Kn + k];
        float mb = g_m[(b * NSPLIT + tid + 32) * Kn + k];
        float da = g_d[(b * NSPLIT + tid) * Kn + k];
        float db = g_d[(b * NSPLIT + tid + 32) * Kn + k];
        float M = fmaxf(ma, mb);
#pragma unroll
        for (int off = 16; off; off >>= 1)
            M = fmaxf(M, __shfl_xor_sync(0xffffffffu, M, off));
        float ta = (ma == NEG_INF) ? 0.f : da * __expf(ma - M);
        float tb = (mb == NEG_INF) ? 0.f : db * __expf(mb - M);
        float D = ta + tb;
#pragma unroll
        for (int off = 16; off; off >>= 1)
            D += __shfl_xor_sync(0xffffffffu, D, off);
        float ca = 0.f, cb = 0.f;
        if (M != NEG_INF && D > 0.f) {
            ca = __expf(ma - M) / D;
            cb = __expf(mb - M) / D;
        }
        coef[tid] = ca;
        coef[tid + 32] = cb;
    }
    __syncthreads();

    const int c0 = cq * 256 + tid * 2;
    ull o = 0ULL;
    const float* accb = g_acc + ((size_t)b * NSPLIT * Kn + k) * Cn;
#pragma unroll
    for (int s = 0; s < NSPLIT; ++s) {
        ull cs = pack2(coef[s], coef[s]);
        ull a = *(const ull*)(accb + (size_t)s * Kn * Cn + c0);
        o = fma2(cs, a, o);
    }
    *(ull*)(out + ((size_t)(b * Kn + k)) * Cn + c0) = o;
}

extern "C" void kernel_launch(void* const* d_in, const int* in_sizes, int n_in,
                              void* d_out, int out_size) {
    const float* x  = (const float*)d_in[0];
    const int* mask = (const int*)d_in[1];
    const float* q  = (const float*)d_in[2];
    float* out      = (float*)d_out;

    cudaFuncSetAttribute(pool_partial_kernel,
                         cudaFuncAttributeMaxDynamicSharedMemorySize, SMEM_TOTAL);
    pool_partial_kernel<<<Bn * NSPLIT, THREADS, SMEM_TOTAL>>>(x, mask, q);
    pool_reduce_kernel<<<Bn * Kn * 4, 128>>>(out);
}

// round 17
// speedup vs baseline: 1.1137x; 1.0018x over previous
#include <cuda_runtime.h>
#include <math.h>

#define Bn 16
#define Ln 4096
#define Cn 1024
#define Kn 16
#define NSPLIT 64
#define CHUNK 64
#define THREADS 256
#define TC 128
#define NTILE 8
#define QSTRIDE 132
#define NEG_INF (__int_as_float(0xff800000))

typedef unsigned long long ull;

__device__ float g_acc[(size_t)Bn * NSPLIT * Kn * Cn];   // 64MB partials
__device__ float g_m[Bn * NSPLIT * Kn];
__device__ float g_d[Bn * NSPLIT * Kn];

__device__ __forceinline__ ull fma2(ull a, ull b, ull c) {
    ull d;
    asm("fma.rn.f32x2 %0, %1, %2, %3;" : "=l"(d) : "l"(a), "l"(b), "l"(c));
    return d;
}
__device__ __forceinline__ float2 unpack2(ull v) {
    float2 f;
    f.x = __uint_as_float((unsigned)(v & 0xffffffffULL));
    f.y = __uint_as_float((unsigned)(v >> 32));
    return f;
}
__device__ __forceinline__ ull pack2(float a, float b) {
    ull v;
    asm("mov.b64 %0, {%1, %2};" : "=l"(v) : "f"(a), "f"(b));
    return v;
}
__device__ __forceinline__ void cp_async16(unsigned int smem, const void* g) {
    asm volatile("cp.async.cg.shared.global [%0], [%1], 16;" :: "r"(smem), "l"(g));
}
__device__ __forceinline__ void cp_commit() {
    asm volatile("cp.async.commit_group;");
}
template <int N>
__device__ __forceinline__ void cp_wait() {
    asm volatile("cp.async.wait_group %0;" :: "n"(N) : "memory");
}
// streaming (evict-first) 8B store / load
__device__ __forceinline__ void stcs8(float* p, float a, float b) {
    ull v = pack2(a, b);
    asm volatile("st.global.cs.b64 [%0], %1;" :: "l"(p), "l"(v) : "memory");
}
__device__ __forceinline__ ull ldcs8(const float* p) {
    ull v;
    asm volatile("ld.global.cs.b64 %0, [%1];" : "=l"(v) : "l"(p));
    return v;
}

// SMEM byte offsets (total 90880 -> 2 blocks/SM)
#define XS0   0
#define XS1   32768
#define QS0   65536
#define QS1   (65536 + 8448)
#define SSOFF 82432
#define W2OFF 86528
#define MKOFF 90624
#define SMEM_TOTAL 90880

extern "C" __global__ void __launch_bounds__(THREADS, 2)
pool_partial_kernel(const float* __restrict__ x,
                    const int* __restrict__ mask,
                    const float* __restrict__ q) {
    extern __shared__ char smem[];
    unsigned int smem_u32 = (unsigned int)__cvta_generic_to_shared(smem);
    float* s_s = (float*)(smem + SSOFF);
    int* mask_s = (int*)(smem + MKOFF);

    const int tid = threadIdx.x;
    const int w = tid >> 5;
    const int lane = tid & 31;
    const int cg = lane & 7;
    const int kg = lane >> 3;
    const int b = blockIdx.x / NSPLIT;
    const int split = blockIdx.x % NSPLIT;
    const int l0 = split * CHUNK;
    const float* xbase = x + ((size_t)b * Ln + l0) * Cn;

    // ---- prefetch tile 0 (x 64x128 + q tile 0) ----
    {
        unsigned int xd = smem_u32 + XS0;
#pragma unroll
        for (int r = 0; r < 8; ++r) {
            int id = tid + THREADS * r;
            int row = id >> 5, c4 = id & 31;
            cp_async16(xd + row * 512 + c4 * 16,
                       xbase + (size_t)row * Cn + c4 * 4);
        }
#pragma unroll
        for (int r = 0; r < 2; ++r) {
            int id = tid + THREADS * r;
            int qrow = id >> 5, qc4 = id & 31;
            cp_async16(smem_u32 + QS0 + qrow * (QSTRIDE * 4) + qc4 * 16,
                       q + qrow * Cn + qc4 * 4);
        }
        cp_commit();
    }
    if (tid < CHUNK) mask_s[tid] = mask[b * Ln + l0 + tid];

    ull acc[8][4];
#pragma unroll
    for (int a = 0; a < 8; ++a)
#pragma unroll
        for (int i = 0; i < 4; ++i) acc[a][i] = 0ULL;

    // ---------------- Phase A: 8 c-tiles of 128 ----------------
    for (int t = 0; t < NTILE; ++t) {
        if (t < NTILE - 1) {
            const int tn = t + 1;
            unsigned int xd = smem_u32 + ((tn & 1) ? XS1 : XS0);
#pragma unroll
            for (int r = 0; r < 8; ++r) {
                int id = tid + THREADS * r;
                int row = id >> 5, c4 = id & 31;
                cp_async16(xd + row * 512 + c4 * 16,
                           xbase + (size_t)row * Cn + tn * TC + c4 * 4);
            }
#pragma unroll
            for (int r = 0; r < 2; ++r) {
                int id = tid + THREADS * r;
                int qrow = id >> 5, qc4 = id & 31;
                cp_async16(smem_u32 + ((tn & 1) ? QS1 : QS0) + qrow * (QSTRIDE * 4) + qc4 * 16,
                           q + qrow * Cn + tn * TC + qc4 * 4);
            }
            cp_commit();
            cp_wait<1>();
        } else {
            cp_wait<0>();
        }
        __syncthreads();

        const float* xs = (const float*)(smem + ((t & 1) ? XS1 : XS0));
        const float* qs = (const float*)(smem + ((t & 1) ? QS1 : QS0));

#pragma unroll
        for (int quad = 0; quad < 4; ++quad) {
            const int cof = cg * 4 + quad * 32;
            ulonglong2 qv[4];
#pragma unroll
            for (int i = 0; i < 4; ++i)
                qv[i] = *(const ulonglong2*)(qs + (kg * 4 + i) * QSTRIDE + cof);
#pragma unroll
            for (int j = 0; j < 8; ++j) {
                ulonglong2 xv = *(const ulonglong2*)(xs + (w * 8 + j) * TC + cof);
#pragma unroll
                for (int i = 0; i < 4; ++i) {
                    acc[j][i] = fma2(xv.x, qv[i].x, acc[j][i]);
                    acc[j][i] = fma2(xv.y, qv[i].y, acc[j][i]);
                }
            }
        }
        __syncthreads();
    }

    // ---- fold + 3-shfl cg reduction + masked write ----
    {
        const float scale = 0.03125f;
#pragma unroll
        for (int j = 0; j < 8; ++j)
#pragma unroll
            for (int i = 0; i < 4; ++i) {
                float2 f = unpack2(acc[j][i]);
                float s = f.x + f.y;
                s += __shfl_xor_sync(0xffffffffu, s, 1);
                s += __shfl_xor_sync(0xffffffffu, s, 2);
                s += __shfl_xor_sync(0xffffffffu, s, 4);
                if (cg == 0) {
                    const int l = w * 8 + j;
                    const int k = kg * 4 + i;
                    s_s[k * CHUNK + l] = mask_s[l] ? (s * scale) : NEG_INF;
                }
            }
    }
    __syncthreads();

    // ---------------- Phase B: 8 warps x 2 k each ----------------
#pragma unroll
    for (int kk = 0; kk < 2; ++kk) {
        const int k = w + kk * 8;
        float v0 = s_s[k * CHUNK + lane];
        float v1 = s_s[k * CHUNK + lane + 32];
        float m = fmaxf(v0, v1);
#pragma unroll
        for (int off = 16; off; off >>= 1)
            m = fmaxf(m, __shfl_xor_sync(0xffffffffu, m, off));
        float e0, e1;
        if (m == NEG_INF) {
            e0 = e1 = 0.f;
        } else {
            e0 = __expf(v0 - m);
            e1 = __expf(v1 - m);
        }
        float d = e0 + e1;
#pragma unroll
        for (int off = 16; off; off >>= 1)
            d += __shfl_xor_sync(0xffffffffu, d, off);
        float* w2f = (float*)(smem + W2OFF);
        {
            int l = lane;
            w2f[(l >> 1) * 32 + k * 2 + (l & 1)] = e0;
            l = lane + 32;
            w2f[(l >> 1) * 32 + k * 2 + (l & 1)] = e1;
        }
        if (lane == 0) {
            g_m[(b * NSPLIT + split) * Kn + k] = m;
            g_d[(b * NSPLIT + split) * Kn + k] = d;
        }
    }
    __syncthreads();

    // -------- Phase C: 2 c-half passes, 32 l-pairs, depth-4 LDG prefetch --------
    const ulonglong2* w2v = (const ulonglong2*)(smem + W2OFF);
    float* ab = g_acc + ((size_t)(b * NSPLIT + split) * Kn) * Cn;
#pragma unroll
    for (int half = 0; half < 2; ++half) {
        const int c0 = half * 512 + tid * 2;
        ull a2[Kn][2];
#pragma unroll
        for (int k = 0; k < Kn; ++k) { a2[k][0] = 0ULL; a2[k][1] = 0ULL; }

        ull xb0[4], xb1[4];
#pragma unroll
        for (int i = 0; i < 4; ++i) {
            xb0[i] = *(const ull*)(xbase + (size_t)(2 * i) * Cn + c0);
            xb1[i] = *(const ull*)(xbase + (size_t)(2 * i + 1) * Cn + c0);
        }

#pragma unroll 4
        for (int lp = 0; lp < 32; ++lp) {
            const int sl = lp & 3;
            float2 fa = unpack2(xb0[sl]);
            float2 fb = unpack2(xb1[sl]);
            ull v0 = pack2(fa.x, fb.x);
            ull v1 = pack2(fa.y, fb.y);
            if (lp < 28) {
                xb0[sl] = *(const ull*)(xbase + (size_t)(2 * (lp + 4)) * Cn + c0);
                xb1[sl] = *(const ull*)(xbase + (size_t)(2 * (lp + 4) + 1) * Cn + c0);
            }
#pragma unroll
            for (int kp = 0; kp < 8; ++kp) {
                ulonglong2 wp = w2v[lp * 8 + kp];
                a2[2 * kp][0]     = fma2(wp.x, v0, a2[2 * kp][0]);
                a2[2 * kp][1]     = fma2(wp.x, v1, a2[2 * kp][1]);
                a2[2 * kp + 1][0] = fma2(wp.y, v0, a2[2 * kp + 1][0]);
                a2[2 * kp + 1][1] = fma2(wp.y, v1, a2[2 * kp + 1][1]);
            }
        }
#pragma unroll
        for (int k = 0; k < Kn; ++k) {
            float2 r0 = unpack2(a2[k][0]);
            float2 r1 = unpack2(a2[k][1]);
            // streaming store: don't pollute L2 (x reuse matters more)
            stcs8(ab + (size_t)k * Cn + c0, r0.x + r0.y, r1.x + r1.y);
        }
    }
}

// ------- Kernel 2: LSE merge, 1024 blocks (b,k,c-quarter), float2/thread -------
extern "C" __global__ void __launch_bounds__(128)
pool_reduce_kernel(float* __restrict__ out) {
    const int bk = blockIdx.x >> 2;
    const int b = bk >> 4;
    const int k = bk & 15;
    const int cq = blockIdx.x & 3;
    const int tid = threadIdx.x;

    __shared__ float coef[NSPLIT];
    if (tid < 32) {
        float ma = g_m[(b * NSPLIT + tid) * Kn + k];
        float mb = g_m[(b * NSPLIT + tid + 32) * Kn + k];
        float da = g_d[(b * NSPLIT + tid) * Kn + k];
        float db = g_d[(b * NSPLIT + tid + 32) * Kn + k];
        float M = fmaxf(ma, mb);
#pragma unroll
        for (int off = 16; off; off >>= 1)
            M = fmaxf(M, __shfl_xor_sync(0xffffffffu, M, off));
        float ta = (ma == NEG_INF) ? 0.f : da * __expf(ma - M);
        float tb = (mb == NEG_INF) ? 0.f : db * __expf(mb - M);
        float D = ta + tb;
#pragma unroll
        for (int off = 16; off; off >>= 1)
            D += __shfl_xor_sync(0xffffffffu, D, off);
        float ca = 0.f, cb = 0.f;
        if (M != NEG_INF && D > 0.f) {
            ca = __expf(ma - M) / D;
            cb = __expf(mb - M) / D;
        }
        coef[tid] = ca;
        coef[tid + 32] = cb;
    }
    __syncthreads();

    const int c0 = cq * 256 + tid * 2;
    ull oa = 0ULL, ob = 0ULL;            // two independent chains
    const float* accb = g_acc + ((size_t)b * NSPLIT * Kn + k) * Cn;
#pragma unroll
    for (int s = 0; s < NSPLIT / 2; ++s) {
        ull ca = pack2(coef[s], coef[s]);
        ull cb = pack2(coef[s + 32], coef[s + 32]);
        ull a = ldcs8(accb + (size_t)s * Kn * Cn + c0);
        ull bb = ldcs8(accb + (size_t)(s + 32) * Kn * Cn + c0);
        oa = fma2(ca, a, oa);
        ob = fma2(cb, bb, ob);
    }
    float2 fa = unpack2(oa);
    float2 fb = unpack2(ob);
    *(float2*)(out + ((size_t)(b * Kn + k)) * Cn + c0) =
        make_float2(fa.x + fb.x, fa.y + fb.y);
}

extern "C" void kernel_launch(void* const* d_in, const int* in_sizes, int n_in,
                              void* d_out, int out_size) {
    const float* x  = (const float*)d_in[0];
    const int* mask = (const int*)d_in[1];
    const float* q  = (const float*)d_in[2];
    float* out      = (float*)d_out;

    cudaFuncSetAttribute(pool_partial_kernel,
                         cudaFuncAttributeMaxDynamicSharedMemorySize, SMEM_TOTAL);
    pool_partial_kernel<<<Bn * NSPLIT, THREADS, SMEM_TOTAL>>>(x, mask, q);
    pool_reduce_kernel<<<Bn * Kn * 4, 128>>>(out);
}